// round 6
// baseline (speedup 1.0000x reference)
#include <cuda_runtime.h>

#define N_NODES 100000
#define N_EDGES 1600000
#define D 128
#define A_DIM 512
#define G_NUM 64

// tall GEMM config: NBLK * KC == N_NODES exactly
#define NBLK 250
#define KC 400
#define TK 25

// ---------------- scratch (device globals) ----------------
__device__ int   g_cnt[N_NODES];
__device__ float g_dis[N_NODES];
__device__ __align__(16) int2  g_db[N_NODES];        // {batch[i], dis[i] as int}
__device__ __align__(16) float g_xn[N_NODES * 4];    // x[i]*dis[i] (3 + pad)
__device__ __align__(16) float g_agg3[N_NODES * 4];  // sum of xn over in-edges
__device__ __align__(16) float g_C[N_NODES * G_NUM]; // Craw[k][g]
__device__ __align__(16) float g_part[NBLK * G_NUM * D];
__device__ int   g_cntg[G_NUM];

// ---------------- helpers ----------------
__device__ __forceinline__ unsigned long long packf2(float v) {
    unsigned long long r;
    unsigned int u = __float_as_uint(v);
    asm("mov.b64 %0, {%1, %1};" : "=l"(r) : "r"(u));
    return r;
}
__device__ __forceinline__ void fma2(unsigned long long& d, unsigned long long a,
                                     unsigned long long b) {
    asm("fma.rn.f32x2 %0, %1, %2, %0;" : "+l"(d) : "l"(a), "l"(b));
}
__device__ __forceinline__ void red_add_v4(float* p, float4 v) {
    unsigned long long gp = (unsigned long long)__cvta_generic_to_global(p);
    asm volatile("red.global.add.v4.f32 [%0], {%1,%2,%3,%4};"
                 :: "l"(gp), "f"(v.x), "f"(v.y), "f"(v.z), "f"(v.w) : "memory");
}

// ---------------- degree histogram ----------------
__global__ void k_hist(const int* __restrict__ dst) {
    int e = blockIdx.x * blockDim.x + threadIdx.x;
    if (e < N_EDGES) atomicAdd(&g_cnt[dst[e]], 1);
}

// ---------------- per-node init ----------------
__global__ void k_dis_init(const float* __restrict__ x, const int* __restrict__ batch) {
    int i = blockIdx.x * blockDim.x + threadIdx.x;
    if (i >= N_NODES) return;
    float dv = rsqrtf((float)(g_cnt[i] + 1));
    g_dis[i] = dv;
    int b = batch[i];
    g_db[i] = make_int2(b, __float_as_int(dv));
    float4 xv;
    xv.x = x[i * 3 + 0] * dv;
    xv.y = x[i * 3 + 1] * dv;
    xv.z = x[i * 3 + 2] * dv;
    xv.w = 0.0f;
    ((float4*)g_xn)[i] = xv;
    g_C[i * G_NUM + b] = dv;          // self term (Craw)
    atomicAdd(&g_cntg[b], 1);
}

// ---------------- per-edge: agg3[d] += xn[s];  Craw[s][batch[d]] += dis[d] ----------------
__global__ void k_edge(const int* __restrict__ src, const int* __restrict__ dst) {
    int e = blockIdx.x * blockDim.x + threadIdx.x;
    if (e >= N_EDGES) return;
    int s = src[e];
    int d = dst[e];
    int2 db = g_db[d];
    float disd = __int_as_float(db.y);
    float4 v = ((const float4*)g_xn)[s];
    red_add_v4(&g_agg3[d * 4], v);
    atomicAdd(&g_C[s * G_NUM + db.x], disd);
}

// ---------------- fused tall GEMM (128 threads, 8g x 8f per thread) ----------------
// part[blk][g][f] = sum_k (dis[k]*Craw[k][g]) * h1r[k][f]
// h1r[k][f] = relu(b1[f] + ((agg3[k]+xn[k])*dis[k]) @ W1) computed in staging.
__global__ __launch_bounds__(128) void k_gemmS(const float* __restrict__ W1,
                                               const float* __restrict__ b1) {
    __shared__ __align__(16) float sC[TK * G_NUM];    // 6.4 KB
    __shared__ __align__(16) float sh[TK * D];        // 12.8 KB
    __shared__ __align__(16) float sW[3 * D];         // W1
    __shared__ __align__(16) float sb[D];             // b1
    int tid = threadIdx.x;
    int g0 = (tid >> 4) * 8;        // 8 groups of 8 graphs
    int f0 = (tid & 15) * 8;        // 16 groups of 8 features

    // stage W1 + b1 once
    if (tid < 3 * D / 4) ((float4*)sW)[tid] = ((const float4*)W1)[tid];
    if (tid >= 96 && tid < 128) ((float4*)sb)[tid - 96] = ((const float4*)b1)[tid - 96];

    unsigned long long acc[8][4];
#pragma unroll
    for (int i = 0; i < 8; i++)
#pragma unroll
        for (int p = 0; p < 4; p++) acc[i][p] = 0ULL;

    int kbase = blockIdx.x * KC;
    __syncthreads();

#pragma unroll 1
    for (int t = 0; t < KC / TK; t++) {
        int k0 = kbase + t * TK;

        // stage C (scaled by dis[k])
        const float4* Cg = (const float4*)(g_C + (size_t)k0 * G_NUM);
        for (int i = tid; i < TK * G_NUM / 4; i += 128) {
            int r = i >> 4;                 // 16 float4 per C row
            float dv = g_dis[k0 + r];
            float4 cc = Cg[i];
            cc.x *= dv; cc.y *= dv; cc.z *= dv; cc.w *= dv;
            ((float4*)sC)[i] = cc;
        }
        // stage h1r computed on the fly (fused layer-1 epilogue)
        for (int i = tid; i < TK * D / 4; i += 128) {
            int r = i >> 5;                 // 32 float4 per h row
            int c = (i & 31) * 4;
            float4 ag = ((const float4*)g_agg3)[k0 + r];
            float4 xv = ((const float4*)g_xn)[k0 + r];
            float dv = g_dis[k0 + r];
            float a0 = (ag.x + xv.x) * dv;
            float a1 = (ag.y + xv.y) * dv;
            float a2 = (ag.z + xv.z) * dv;
            float4 w0 = *(const float4*)(sW + 0 * D + c);
            float4 w1 = *(const float4*)(sW + 1 * D + c);
            float4 w2 = *(const float4*)(sW + 2 * D + c);
            float4 bv = *(const float4*)(sb + c);
            float4 hv;
            hv.x = fmaxf(bv.x + a0 * w0.x + a1 * w1.x + a2 * w2.x, 0.0f);
            hv.y = fmaxf(bv.y + a0 * w0.y + a1 * w1.y + a2 * w2.y, 0.0f);
            hv.z = fmaxf(bv.z + a0 * w0.z + a1 * w1.z + a2 * w2.z, 0.0f);
            hv.w = fmaxf(bv.w + a0 * w0.w + a1 * w1.w + a2 * w2.w, 0.0f);
            ((float4*)sh)[i] = hv;
        }
        __syncthreads();

#pragma unroll 1
        for (int kk = 0; kk < TK; kk++) {
            float4 ca = *(const float4*)(sC + kk * G_NUM + g0);
            float4 cb = *(const float4*)(sC + kk * G_NUM + g0 + 4);
            ulonglong2 h01 = *(const ulonglong2*)(sh + kk * D + f0);
            ulonglong2 h23 = *(const ulonglong2*)(sh + kk * D + f0 + 4);
            unsigned long long hp[4] = {h01.x, h01.y, h23.x, h23.y};
            unsigned long long cp[8];
            cp[0] = packf2(ca.x); cp[1] = packf2(ca.y);
            cp[2] = packf2(ca.z); cp[3] = packf2(ca.w);
            cp[4] = packf2(cb.x); cp[5] = packf2(cb.y);
            cp[6] = packf2(cb.z); cp[7] = packf2(cb.w);
#pragma unroll
            for (int i = 0; i < 8; i++)
#pragma unroll
                for (int p = 0; p < 4; p++) fma2(acc[i][p], cp[i], hp[p]);
        }
        __syncthreads();
    }

    float* base = g_part + (size_t)blockIdx.x * G_NUM * D;
#pragma unroll
    for (int i = 0; i < 8; i++)
#pragma unroll
        for (int p = 0; p < 4; p++)
            *(unsigned long long*)(base + (g0 + i) * D + f0 + p * 2) = acc[i][p];
}

// ---------------- reduce partials + mean + @W2+b2 + @Wf+bf  (block per graph, 512 thr) ----------------
__global__ __launch_bounds__(512) void k_pwq(const float* __restrict__ W2,
                                             const float* __restrict__ b2,
                                             const float* __restrict__ Wf,
                                             const float* __restrict__ bf,
                                             float* __restrict__ q) {
    __shared__ float stmp[512];
    __shared__ float sT[D];
    __shared__ float sge[D];
    int g = blockIdx.x;
    int tid = threadIdx.x;    // 512
    int f = tid & 127, quart = tid >> 7;

    float s = 0.0f;
    for (int b = quart; b < NBLK; b += 4)
        s += g_part[(size_t)b * G_NUM * D + g * D + f];
    stmp[tid] = s;
    __syncthreads();
    if (quart == 0) {
        float cnt = fmaxf((float)g_cntg[g], 1.0f);
        sT[f] = (stmp[f] + stmp[f + 128] + stmp[f + 256] + stmp[f + 384]) / cnt;
    }
    __syncthreads();

    if (tid < D) {
        float acc = b2[tid];
#pragma unroll 16
        for (int k = 0; k < D; k++) acc += sT[k] * W2[k * D + tid];
        sge[tid] = acc;
    }
    __syncthreads();

    {
        int a = tid;            // 512 threads == A_DIM outputs
        float acc = bf[a];
#pragma unroll 16
        for (int k = 0; k < D; k++) acc += sge[k] * Wf[k * A_DIM + a];
        q[g * A_DIM + a] = acc;
    }
}

// ---------------- launch ----------------
extern "C" void kernel_launch(void* const* d_in, const int* in_sizes, int n_in,
                              void* d_out, int out_size) {
    const float* x     = (const float*)d_in[0];
    const int*   ei    = (const int*)  d_in[1];
    const int*   batch = (const int*)  d_in[2];
    const float* W1    = (const float*)d_in[3];
    const float* b1    = (const float*)d_in[4];
    const float* W2    = (const float*)d_in[5];
    const float* b2    = (const float*)d_in[6];
    const float* Wf    = (const float*)d_in[7];
    const float* bf    = (const float*)d_in[8];
    float* q = (float*)d_out;

    const int* src = ei;
    const int* dst = ei + N_EDGES;

    void *pc, *pC, *pa, *pg;
    cudaGetSymbolAddress(&pc, g_cnt);
    cudaGetSymbolAddress(&pC, g_C);
    cudaGetSymbolAddress(&pa, g_agg3);
    cudaGetSymbolAddress(&pg, g_cntg);

    cudaMemsetAsync(pc, 0, N_NODES * sizeof(int));
    cudaMemsetAsync(pC, 0, (size_t)N_NODES * G_NUM * sizeof(float));
    cudaMemsetAsync(pa, 0, (size_t)N_NODES * 4 * sizeof(float));
    cudaMemsetAsync(pg, 0, G_NUM * sizeof(int));

    k_hist<<<(N_EDGES + 255) / 256, 256>>>(dst);
    k_dis_init<<<(N_NODES + 255) / 256, 256>>>(x, batch);
    k_edge<<<(N_EDGES + 255) / 256, 256>>>(src, dst);
    k_gemmS<<<NBLK, 128>>>(W1, b1);
    k_pwq<<<G_NUM, 512>>>(W2, b2, Wf, bf, q);
}

// round 7
// speedup vs baseline: 1.1001x; 1.1001x over previous
#include <cuda_runtime.h>

#define N_NODES 100000
#define N_EDGES 1600000
#define D 128
#define A_DIM 512
#define G_NUM 64

// tall GEMM config: NBLK * KC == N_NODES exactly
#define NBLK 800
#define KC 125
#define TK 25

// ---------------- scratch (device globals) ----------------
__device__ int   g_cnt[N_NODES];
__device__ float g_dis[N_NODES];
__device__ __align__(16) int2  g_db[N_NODES];        // {batch[i], dis[i] as int}
__device__ __align__(16) float g_xn[N_NODES * 4];    // x[i]*dis[i] (3 + pad)
__device__ __align__(16) float g_agg3[N_NODES * 4];  // sum of xn over in-edges
__device__ __align__(16) float g_C[N_NODES * G_NUM]; // Craw[k][g]
__device__ __align__(16) float g_part[NBLK * G_NUM * D];
__device__ int   g_cntg[G_NUM];

// ---------------- helpers ----------------
__device__ __forceinline__ unsigned long long packf2(float v) {
    unsigned long long r;
    unsigned int u = __float_as_uint(v);
    asm("mov.b64 %0, {%1, %1};" : "=l"(r) : "r"(u));
    return r;
}
__device__ __forceinline__ void fma2(unsigned long long& d, unsigned long long a,
                                     unsigned long long b) {
    asm("fma.rn.f32x2 %0, %1, %2, %0;" : "+l"(d) : "l"(a), "l"(b));
}
__device__ __forceinline__ void red_add_v4(float* p, float4 v) {
    unsigned long long gp = (unsigned long long)__cvta_generic_to_global(p);
    asm volatile("red.global.add.v4.f32 [%0], {%1,%2,%3,%4};"
                 :: "l"(gp), "f"(v.x), "f"(v.y), "f"(v.z), "f"(v.w) : "memory");
}

// ---------------- degree histogram ----------------
__global__ void k_hist(const int* __restrict__ dst) {
    int e = blockIdx.x * blockDim.x + threadIdx.x;
    if (e < N_EDGES) atomicAdd(&g_cnt[dst[e]], 1);
}

// ---------------- per-node init ----------------
__global__ void k_dis_init(const float* __restrict__ x, const int* __restrict__ batch) {
    int i = blockIdx.x * blockDim.x + threadIdx.x;
    if (i >= N_NODES) return;
    float dv = rsqrtf((float)(g_cnt[i] + 1));
    g_dis[i] = dv;
    int b = batch[i];
    g_db[i] = make_int2(b, __float_as_int(dv));
    float4 xv;
    xv.x = x[i * 3 + 0] * dv;
    xv.y = x[i * 3 + 1] * dv;
    xv.z = x[i * 3 + 2] * dv;
    xv.w = 0.0f;
    ((float4*)g_xn)[i] = xv;
    g_C[i * G_NUM + b] = dv;          // self term (Craw)
    atomicAdd(&g_cntg[b], 1);
}

// ---------------- per-edge: agg3[d] += xn[s];  Craw[s][batch[d]] += dis[d] ----------------
__global__ void k_edge(const int* __restrict__ src, const int* __restrict__ dst) {
    int e = blockIdx.x * blockDim.x + threadIdx.x;
    if (e >= N_EDGES) return;
    int s = src[e];
    int d = dst[e];
    int2 db = g_db[d];
    float disd = __int_as_float(db.y);
    float4 v = ((const float4*)g_xn)[s];
    red_add_v4(&g_agg3[d * 4], v);
    atomicAdd(&g_C[s * G_NUM + db.x], disd);
}

// ---------------- fused tall GEMM (128 threads, 8g x 8f per thread, deep K-split) ----------------
// part[blk][g][f] = sum_k (dis[k]*Craw[k][g]) * h1r[k][f]
// h1r[k][f] = relu(b1[f] + ((agg3[k]+xn[k])*dis[k]) @ W1) computed in staging.
__global__ __launch_bounds__(128) void k_gemmS(const float* __restrict__ W1,
                                               const float* __restrict__ b1) {
    __shared__ __align__(16) float sC[TK * G_NUM];    // 6.4 KB
    __shared__ __align__(16) float sh[TK * D];        // 12.8 KB
    __shared__ __align__(16) float sW[3 * D];         // W1
    __shared__ __align__(16) float sb[D];             // b1
    int tid = threadIdx.x;
    int g0 = (tid >> 4) * 8;        // 8 groups of 8 graphs
    int f0 = (tid & 15) * 8;        // 16 groups of 8 features

    // stage W1 + b1 once
    if (tid < 3 * D / 4) ((float4*)sW)[tid] = ((const float4*)W1)[tid];
    if (tid >= 96 && tid < 128) ((float4*)sb)[tid - 96] = ((const float4*)b1)[tid - 96];

    unsigned long long acc[8][4];
#pragma unroll
    for (int i = 0; i < 8; i++)
#pragma unroll
        for (int p = 0; p < 4; p++) acc[i][p] = 0ULL;

    int kbase = blockIdx.x * KC;
    __syncthreads();

#pragma unroll 1
    for (int t = 0; t < KC / TK; t++) {
        int k0 = kbase + t * TK;

        // stage C (scaled by dis[k])
        const float4* Cg = (const float4*)(g_C + (size_t)k0 * G_NUM);
        for (int i = tid; i < TK * G_NUM / 4; i += 128) {
            int r = i >> 4;                 // 16 float4 per C row
            float dv = g_dis[k0 + r];
            float4 cc = Cg[i];
            cc.x *= dv; cc.y *= dv; cc.z *= dv; cc.w *= dv;
            ((float4*)sC)[i] = cc;
        }
        // stage h1r computed on the fly (fused layer-1 epilogue)
        for (int i = tid; i < TK * D / 4; i += 128) {
            int r = i >> 5;                 // 32 float4 per h row
            int c = (i & 31) * 4;
            float4 ag = ((const float4*)g_agg3)[k0 + r];
            float4 xv = ((const float4*)g_xn)[k0 + r];
            float dv = g_dis[k0 + r];
            float a0 = (ag.x + xv.x) * dv;
            float a1 = (ag.y + xv.y) * dv;
            float a2 = (ag.z + xv.z) * dv;
            float4 w0 = *(const float4*)(sW + 0 * D + c);
            float4 w1 = *(const float4*)(sW + 1 * D + c);
            float4 w2 = *(const float4*)(sW + 2 * D + c);
            float4 bv = *(const float4*)(sb + c);
            float4 hv;
            hv.x = fmaxf(bv.x + a0 * w0.x + a1 * w1.x + a2 * w2.x, 0.0f);
            hv.y = fmaxf(bv.y + a0 * w0.y + a1 * w1.y + a2 * w2.y, 0.0f);
            hv.z = fmaxf(bv.z + a0 * w0.z + a1 * w1.z + a2 * w2.z, 0.0f);
            hv.w = fmaxf(bv.w + a0 * w0.w + a1 * w1.w + a2 * w2.w, 0.0f);
            ((float4*)sh)[i] = hv;
        }
        __syncthreads();

#pragma unroll 1
        for (int kk = 0; kk < TK; kk++) {
            float4 ca = *(const float4*)(sC + kk * G_NUM + g0);
            float4 cb = *(const float4*)(sC + kk * G_NUM + g0 + 4);
            ulonglong2 h01 = *(const ulonglong2*)(sh + kk * D + f0);
            ulonglong2 h23 = *(const ulonglong2*)(sh + kk * D + f0 + 4);
            unsigned long long hp[4] = {h01.x, h01.y, h23.x, h23.y};
            unsigned long long cp[8];
            cp[0] = packf2(ca.x); cp[1] = packf2(ca.y);
            cp[2] = packf2(ca.z); cp[3] = packf2(ca.w);
            cp[4] = packf2(cb.x); cp[5] = packf2(cb.y);
            cp[6] = packf2(cb.z); cp[7] = packf2(cb.w);
#pragma unroll
            for (int i = 0; i < 8; i++)
#pragma unroll
                for (int p = 0; p < 4; p++) fma2(acc[i][p], cp[i], hp[p]);
        }
        __syncthreads();
    }

    float* base = g_part + (size_t)blockIdx.x * G_NUM * D;
#pragma unroll
    for (int i = 0; i < 8; i++)
#pragma unroll
        for (int p = 0; p < 4; p++)
            *(unsigned long long*)(base + (g0 + i) * D + f0 + p * 2) = acc[i][p];
}

// ---------------- reduce partials + mean + @W2+b2 + @Wf+bf  (block per graph, 512 thr) ----------------
__global__ __launch_bounds__(512) void k_pwq(const float* __restrict__ W2,
                                             const float* __restrict__ b2,
                                             const float* __restrict__ Wf,
                                             const float* __restrict__ bf,
                                             float* __restrict__ q) {
    __shared__ float stmp[512];
    __shared__ float sT[D];
    __shared__ float sge[D];
    int g = blockIdx.x;
    int tid = threadIdx.x;    // 512
    int f = tid & 127, quart = tid >> 7;

    float s = 0.0f;
    for (int b = quart; b < NBLK; b += 4)
        s += g_part[(size_t)b * G_NUM * D + g * D + f];
    stmp[tid] = s;
    __syncthreads();
    if (quart == 0) {
        float cnt = fmaxf((float)g_cntg[g], 1.0f);
        sT[f] = (stmp[f] + stmp[f + 128] + stmp[f + 256] + stmp[f + 384]) / cnt;
    }
    __syncthreads();

    if (tid < D) {
        float acc = b2[tid];
#pragma unroll 16
        for (int k = 0; k < D; k++) acc += sT[k] * W2[k * D + tid];
        sge[tid] = acc;
    }
    __syncthreads();

    {
        int a = tid;            // 512 threads == A_DIM outputs
        float acc = bf[a];
#pragma unroll 16
        for (int k = 0; k < D; k++) acc += sge[k] * Wf[k * A_DIM + a];
        q[g * A_DIM + a] = acc;
    }
}

// ---------------- launch ----------------
extern "C" void kernel_launch(void* const* d_in, const int* in_sizes, int n_in,
                              void* d_out, int out_size) {
    const float* x     = (const float*)d_in[0];
    const int*   ei    = (const int*)  d_in[1];
    const int*   batch = (const int*)  d_in[2];
    const float* W1    = (const float*)d_in[3];
    const float* b1    = (const float*)d_in[4];
    const float* W2    = (const float*)d_in[5];
    const float* b2    = (const float*)d_in[6];
    const float* Wf    = (const float*)d_in[7];
    const float* bf    = (const float*)d_in[8];
    float* q = (float*)d_out;

    const int* src = ei;
    const int* dst = ei + N_EDGES;

    void *pc, *pC, *pa, *pg;
    cudaGetSymbolAddress(&pc, g_cnt);
    cudaGetSymbolAddress(&pC, g_C);
    cudaGetSymbolAddress(&pa, g_agg3);
    cudaGetSymbolAddress(&pg, g_cntg);

    cudaMemsetAsync(pc, 0, N_NODES * sizeof(int));
    cudaMemsetAsync(pC, 0, (size_t)N_NODES * G_NUM * sizeof(float));
    cudaMemsetAsync(pa, 0, (size_t)N_NODES * 4 * sizeof(float));
    cudaMemsetAsync(pg, 0, G_NUM * sizeof(int));

    k_hist<<<(N_EDGES + 255) / 256, 256>>>(dst);
    k_dis_init<<<(N_NODES + 255) / 256, 256>>>(x, batch);
    k_edge<<<(N_EDGES + 255) / 256, 256>>>(src, dst);
    k_gemmS<<<NBLK, 128>>>(W1, b1);
    k_pwq<<<G_NUM, 512>>>(W2, b2, Wf, bf, q);
}

// round 8
// speedup vs baseline: 1.1376x; 1.0341x over previous
#include <cuda_runtime.h>

#define N_NODES 100000
#define N_EDGES 1600000
#define D 128
#define A_DIM 512
#define G_NUM 64

// tall GEMM config: NBLK * KC == N_NODES exactly
#define NBLK 800
#define KC 125
#define TK 25

// ---------------- scratch (device globals) ----------------
__device__ int   g_cnt[N_NODES];
__device__ float g_dis[N_NODES];
__device__ __align__(16) int2  g_db[N_NODES];        // {batch[i], dis[i] as int}
__device__ __align__(16) float g_xn[N_NODES * 4];    // x[i]*dis[i] (3 + pad)
__device__ __align__(16) float g_agg3[N_NODES * 4];  // self + sum of xn over in-edges
__device__ __align__(16) float g_C[N_NODES * G_NUM]; // Craw[k][g]
__device__ __align__(16) float g_part[NBLK * G_NUM * D];
__device__ int   g_cntg[G_NUM];

// ---------------- helpers ----------------
__device__ __forceinline__ unsigned long long packf2(float v) {
    unsigned long long r;
    unsigned int u = __float_as_uint(v);
    asm("mov.b64 %0, {%1, %1};" : "=l"(r) : "r"(u));
    return r;
}
__device__ __forceinline__ void fma2(unsigned long long& d, unsigned long long a,
                                     unsigned long long b) {
    asm("fma.rn.f32x2 %0, %1, %2, %0;" : "+l"(d) : "l"(a), "l"(b));
}
__device__ __forceinline__ void red_add_v4(float* p, float4 v) {
    unsigned long long gp = (unsigned long long)__cvta_generic_to_global(p);
    asm volatile("red.global.add.v4.f32 [%0], {%1,%2,%3,%4};"
                 :: "l"(gp), "f"(v.x), "f"(v.y), "f"(v.z), "f"(v.w) : "memory");
}

// ---------------- degree histogram ----------------
__global__ void k_hist(const int* __restrict__ dst) {
    int e = blockIdx.x * blockDim.x + threadIdx.x;
    if (e < N_EDGES) atomicAdd(&g_cnt[dst[e]], 1);
}

// ---------------- fused init: C rows (single touch, self term in place) + per-node state ----------------
__global__ void k_dis_init(const float* __restrict__ x, const int* __restrict__ batch) {
    int idx = blockIdx.x * blockDim.x + threadIdx.x;   // over N_NODES*16 float4 slots
    if (idx >= N_NODES * 16) return;
    int node = idx >> 4;
    int slot = idx & 15;
    float dv = rsqrtf((float)(g_cnt[node] + 1));
    int b = batch[node];
    float4 v = make_float4(0.f, 0.f, 0.f, 0.f);
    int gbase = slot * 4;
    if (b - gbase == 0) v.x = dv;
    else if (b - gbase == 1) v.y = dv;
    else if (b - gbase == 2) v.z = dv;
    else if (b - gbase == 3) v.w = dv;
    ((float4*)g_C)[idx] = v;
    if (slot == 0) {
        g_dis[node] = dv;
        g_db[node] = make_int2(b, __float_as_int(dv));
        float4 xv;
        xv.x = x[node * 3 + 0] * dv;
        xv.y = x[node * 3 + 1] * dv;
        xv.z = x[node * 3 + 2] * dv;
        xv.w = 0.0f;
        ((float4*)g_xn)[node] = xv;
        ((float4*)g_agg3)[node] = xv;      // self-loop term pre-seeded
        atomicAdd(&g_cntg[b], 1);
    }
}

// ---------------- per-edge: agg3[d] += xn[s];  Craw[s][batch[d]] += dis[d] ----------------
__global__ void k_edge(const int* __restrict__ src, const int* __restrict__ dst) {
    int e = blockIdx.x * blockDim.x + threadIdx.x;
    if (e >= N_EDGES) return;
    int s = src[e];
    int d = dst[e];
    int2 db = g_db[d];
    float disd = __int_as_float(db.y);
    float4 v = ((const float4*)g_xn)[s];
    red_add_v4(&g_agg3[d * 4], v);
    atomicAdd(&g_C[s * G_NUM + db.x], disd);
}

// ---------------- fused tall GEMM (128 threads, 8g x 8f per thread, 5 blocks/SM) ----------------
// part[blk][g][f] = sum_k (dis[k]*Craw[k][g]) * h1r[k][f]
// h1r[k][f] = relu(b1[f] + (agg3[k]*dis[k]) @ W1) computed in staging.
__global__ __launch_bounds__(128, 5) void k_gemmS(const float* __restrict__ W1,
                                                  const float* __restrict__ b1) {
    __shared__ __align__(16) float sC[TK * G_NUM];    // 6.4 KB
    __shared__ __align__(16) float sh[TK * D];        // 12.8 KB
    __shared__ __align__(16) float sW[3 * D];         // W1
    __shared__ __align__(16) float sb[D];             // b1
    int tid = threadIdx.x;
    int g0 = (tid >> 4) * 8;        // 8 groups of 8 graphs
    int f0 = (tid & 15) * 8;        // 16 groups of 8 features

    // stage W1 + b1 once
    if (tid < 3 * D / 4) ((float4*)sW)[tid] = ((const float4*)W1)[tid];
    if (tid >= 96 && tid < 128) ((float4*)sb)[tid - 96] = ((const float4*)b1)[tid - 96];

    unsigned long long acc[8][4];
#pragma unroll
    for (int i = 0; i < 8; i++)
#pragma unroll
        for (int p = 0; p < 4; p++) acc[i][p] = 0ULL;

    int kbase = blockIdx.x * KC;
    __syncthreads();

#pragma unroll 1
    for (int t = 0; t < KC / TK; t++) {
        int k0 = kbase + t * TK;

        // stage C (scaled by dis[k])
        const float4* Cg = (const float4*)(g_C + (size_t)k0 * G_NUM);
        for (int i = tid; i < TK * G_NUM / 4; i += 128) {
            int r = i >> 4;                 // 16 float4 per C row
            float dv = g_dis[k0 + r];
            float4 cc = Cg[i];
            cc.x *= dv; cc.y *= dv; cc.z *= dv; cc.w *= dv;
            ((float4*)sC)[i] = cc;
        }
        // stage h1r computed on the fly (fused layer-1 epilogue)
        for (int i = tid; i < TK * D / 4; i += 128) {
            int r = i >> 5;                 // 32 float4 per h row
            int c = (i & 31) * 4;
            float4 ag = ((const float4*)g_agg3)[k0 + r];
            float dv = g_dis[k0 + r];
            float a0 = ag.x * dv;
            float a1 = ag.y * dv;
            float a2 = ag.z * dv;
            float4 w0 = *(const float4*)(sW + 0 * D + c);
            float4 w1 = *(const float4*)(sW + 1 * D + c);
            float4 w2 = *(const float4*)(sW + 2 * D + c);
            float4 bv = *(const float4*)(sb + c);
            float4 hv;
            hv.x = fmaxf(bv.x + a0 * w0.x + a1 * w1.x + a2 * w2.x, 0.0f);
            hv.y = fmaxf(bv.y + a0 * w0.y + a1 * w1.y + a2 * w2.y, 0.0f);
            hv.z = fmaxf(bv.z + a0 * w0.z + a1 * w1.z + a2 * w2.z, 0.0f);
            hv.w = fmaxf(bv.w + a0 * w0.w + a1 * w1.w + a2 * w2.w, 0.0f);
            ((float4*)sh)[i] = hv;
        }
        __syncthreads();

#pragma unroll 1
        for (int kk = 0; kk < TK; kk++) {
            float4 ca = *(const float4*)(sC + kk * G_NUM + g0);
            float4 cb = *(const float4*)(sC + kk * G_NUM + g0 + 4);
            ulonglong2 h01 = *(const ulonglong2*)(sh + kk * D + f0);
            ulonglong2 h23 = *(const ulonglong2*)(sh + kk * D + f0 + 4);
            unsigned long long hp[4] = {h01.x, h01.y, h23.x, h23.y};
            unsigned long long cp[8];
            cp[0] = packf2(ca.x); cp[1] = packf2(ca.y);
            cp[2] = packf2(ca.z); cp[3] = packf2(ca.w);
            cp[4] = packf2(cb.x); cp[5] = packf2(cb.y);
            cp[6] = packf2(cb.z); cp[7] = packf2(cb.w);
#pragma unroll
            for (int i = 0; i < 8; i++)
#pragma unroll
                for (int p = 0; p < 4; p++) fma2(acc[i][p], cp[i], hp[p]);
        }
        __syncthreads();
    }

    float* base = g_part + (size_t)blockIdx.x * G_NUM * D;
#pragma unroll
    for (int i = 0; i < 8; i++)
#pragma unroll
        for (int p = 0; p < 4; p++)
            *(unsigned long long*)(base + (g0 + i) * D + f0 + p * 2) = acc[i][p];
}

// ---------------- reduce partials + mean + @W2+b2 + @Wf+bf  (block per graph, 512 thr) ----------------
__global__ __launch_bounds__(512) void k_pwq(const float* __restrict__ W2,
                                             const float* __restrict__ b2,
                                             const float* __restrict__ Wf,
                                             const float* __restrict__ bf,
                                             float* __restrict__ q) {
    __shared__ float stmp[512];
    __shared__ float sT[D];
    __shared__ float sge[D];
    int g = blockIdx.x;
    int tid = threadIdx.x;    // 512
    int f = tid & 127, quart = tid >> 7;

    float s = 0.0f;
    for (int b = quart; b < NBLK; b += 4)
        s += g_part[(size_t)b * G_NUM * D + g * D + f];
    stmp[tid] = s;
    __syncthreads();
    if (quart == 0) {
        float cnt = fmaxf((float)g_cntg[g], 1.0f);
        sT[f] = (stmp[f] + stmp[f + 128] + stmp[f + 256] + stmp[f + 384]) / cnt;
    }
    __syncthreads();

    if (tid < D) {
        float acc = b2[tid];
#pragma unroll 16
        for (int k = 0; k < D; k++) acc += sT[k] * W2[k * D + tid];
        sge[tid] = acc;
    }
    __syncthreads();

    {
        int a = tid;            // 512 threads == A_DIM outputs
        float acc = bf[a];
#pragma unroll 16
        for (int k = 0; k < D; k++) acc += sge[k] * Wf[k * A_DIM + a];
        q[g * A_DIM + a] = acc;
    }
}

// ---------------- launch ----------------
extern "C" void kernel_launch(void* const* d_in, const int* in_sizes, int n_in,
                              void* d_out, int out_size) {
    const float* x     = (const float*)d_in[0];
    const int*   ei    = (const int*)  d_in[1];
    const int*   batch = (const int*)  d_in[2];
    const float* W1    = (const float*)d_in[3];
    const float* b1    = (const float*)d_in[4];
    const float* W2    = (const float*)d_in[5];
    const float* b2    = (const float*)d_in[6];
    const float* Wf    = (const float*)d_in[7];
    const float* bf    = (const float*)d_in[8];
    float* q = (float*)d_out;

    const int* src = ei;
    const int* dst = ei + N_EDGES;

    void *pc, *pg;
    cudaGetSymbolAddress(&pc, g_cnt);
    cudaGetSymbolAddress(&pg, g_cntg);

    cudaMemsetAsync(pc, 0, N_NODES * sizeof(int));
    cudaMemsetAsync(pg, 0, G_NUM * sizeof(int));

    k_hist<<<(N_EDGES + 255) / 256, 256>>>(dst);
    k_dis_init<<<(N_NODES * 16 + 255) / 256, 256>>>(x, batch);
    k_edge<<<(N_EDGES + 255) / 256, 256>>>(src, dst);
    k_gemmS<<<NBLK, 128>>>(W1, b1);
    k_pwq<<<G_NUM, 512>>>(W2, b2, Wf, bf, q);
}